// round 11
// baseline (speedup 1.0000x reference)
#include <cuda_runtime.h>
#include <math.h>

#define NV   500000
#define ND   128
#define NEDGE 1000000
#define NKK  8
#define NH   8
#define NC   16

// ---------------- scratch (static device globals; no runtime allocation) ----
__device__ __align__(256) float g_proj[NV];
__device__ __align__(256) float g_dinv[NV];                 // deg, then dinv
__device__ __align__(256) float g_M   [(size_t)NV * 16];    // dense-GEMM result (stride 8 or 16)
__device__ __align__(256) float g_outA[(size_t)NV * 16];    // spmm accum, stride 8 (layers 1,2)
__device__ __align__(256) float g_outB[(size_t)NV * 16];    // spmm accum, stride 16 (layer 3)
__device__ __align__(256) int2  g_SI[NEDGE];                // packed (Se, Ie)
__device__ __align__(256) float g_w [NEDGE];
__device__ int g_is64;

// ---------------- helpers ---------------------------------------------------
__device__ __forceinline__ void red_add4(float* p, float a, float b, float c, float d) {
    asm volatile("red.global.add.v4.f32 [%0], {%1, %2, %3, %4};"
                 :: "l"(__cvta_generic_to_global(p)),
                    "f"(a), "f"(b), "f"(c), "f"(d)
                 : "memory");
}

// ---------------- K0: detect whether E is int64 or int32 --------------------
// jnp.int64 annotation may silently produce int32 under default JAX x64=off.
// If E is int64 (indices < 2^31), every odd 32-bit word is 0. Genuine int32
// index data has ~zero probability of 1024 all-zero odd words.
__global__ void k_detect(const int* __restrict__ E32) {
    __shared__ int any;
    if (threadIdx.x == 0) any = 0;
    __syncthreads();
    for (int i = threadIdx.x; i < 1024; i += blockDim.x)
        if (E32[2 * i + 1] != 0) any = 1;
    __syncthreads();
    if (threadIdx.x == 0) g_is64 = (any == 0) ? 1 : 0;
}

// ---------------- K1: proj = X@rv  AND  M1 = X@W1  (single pass over X) -----
// one warp per row; lane holds one float4 (128 floats / 32 lanes)
__global__ void __launch_bounds__(256)
k_proj_xw1(const float* __restrict__ X,
           const float* __restrict__ rv,
           const float* __restrict__ W1) {
    __shared__ float s_rv[ND];
    __shared__ float s_w1t[NH * ND];   // transposed: [j][i] for conflict-free LDS.128
    for (int i = threadIdx.x; i < ND; i += blockDim.x) s_rv[i] = rv[i];
    for (int i = threadIdx.x; i < ND * NH; i += blockDim.x) {
        int r = i >> 3, j = i & 7;     // W1[r][j], row-major [D,H1]
        s_w1t[j * ND + r] = W1[i];
    }
    __syncthreads();

    int warp = (blockIdx.x * blockDim.x + threadIdx.x) >> 5;
    int lane = threadIdx.x & 31;
    if (warp >= NV) return;

    float4 x  = *(const float4*)(X + (size_t)warp * ND + lane * 4);
    float4 r4 = *(const float4*)(s_rv + lane * 4);
    float a0 = x.x * r4.x + x.y * r4.y + x.z * r4.z + x.w * r4.w;
    float aj[NH];
#pragma unroll
    for (int j = 0; j < NH; j++) {
        float4 w = *(const float4*)(s_w1t + j * ND + lane * 4);
        aj[j] = x.x * w.x + x.y * w.y + x.z * w.z + x.w * w.w;
    }
#pragma unroll
    for (int off = 16; off; off >>= 1) {
        a0 += __shfl_xor_sync(0xffffffffu, a0, off);
#pragma unroll
        for (int j = 0; j < NH; j++)
            aj[j] += __shfl_xor_sync(0xffffffffu, aj[j], off);
    }
    if (lane == 0) {
        g_proj[warp] = a0;
        g_dinv[warp] = 1.0f;   // deg init (identity term)
        *(float4*)(g_M + (size_t)warp * NH)     = make_float4(aj[0], aj[1], aj[2], aj[3]);
        *(float4*)(g_M + (size_t)warp * NH + 4) = make_float4(aj[4], aj[5], aj[6], aj[7]);
    }
}

// ---------------- K2: per-hyperedge argmax/argmin + degree atomics ----------
// 2 edges per thread for higher DRAM MLP on the E stream.
__device__ __forceinline__ void edge_one(const void* Eraw, int e, int is64) {
    int idx[NKK];
    if (is64) {
        const longlong2* p = (const longlong2*)((const long long*)Eraw + (size_t)e * NKK);
        longlong2 c0 = p[0], c1 = p[1], c2 = p[2], c3 = p[3];
        idx[0]=(int)c0.x; idx[1]=(int)c0.y; idx[2]=(int)c1.x; idx[3]=(int)c1.y;
        idx[4]=(int)c2.x; idx[5]=(int)c2.y; idx[6]=(int)c3.x; idx[7]=(int)c3.y;
    } else {
        const int4* p = (const int4*)((const int*)Eraw + (size_t)e * NKK);
        int4 c0 = p[0], c1 = p[1];
        idx[0]=c0.x; idx[1]=c0.y; idx[2]=c0.z; idx[3]=c0.w;
        idx[4]=c1.x; idx[5]=c1.y; idx[6]=c1.z; idx[7]=c1.w;
    }
    float pv[NKK];
#pragma unroll
    for (int t = 0; t < NKK; t++) pv[t] = __ldg(g_proj + idx[t]);

    int s = idx[0], im = idx[0];
    float pmax = pv[0], pmin = pv[0];
#pragma unroll
    for (int t = 1; t < NKK; t++) {
        if (pv[t] > pmax) { pmax = pv[t]; s  = idx[t]; }  // first-occurrence max (jnp.argmax)
        if (pv[t] < pmin) { pmin = pv[t]; im = idx[t]; }  // first-occurrence min
    }
    g_SI[e] = make_int2(s, im);
    atomicAdd(g_dinv + s,  0.125f);
    atomicAdd(g_dinv + im, 0.125f);
}

__global__ void __launch_bounds__(256)
k_edges(const void* __restrict__ Eraw) {
    int t = blockIdx.x * blockDim.x + threadIdx.x;
    int is64 = g_is64;
    int e0 = t * 2;
    if (e0 < NEDGE)     edge_one(Eraw, e0, is64);
    if (e0 + 1 < NEDGE) edge_one(Eraw, e0 + 1, is64);
}

// ---------------- K3: dinv = rsqrt(deg); out1 = dinv^2 * M1 -----------------
__global__ void __launch_bounds__(256) k_dinv_scale() {
    int v = blockIdx.x * blockDim.x + threadIdx.x;
    if (v >= NV) return;
    float d = rsqrtf(g_dinv[v]);
    g_dinv[v] = d;
    float dd = d * d;
    float4 m0 = *(const float4*)(g_M + (size_t)v * NH);
    float4 m1 = *(const float4*)(g_M + (size_t)v * NH + 4);
    m0.x *= dd; m0.y *= dd; m0.z *= dd; m0.w *= dd;
    m1.x *= dd; m1.y *= dd; m1.z *= dd; m1.w *= dd;
    *(float4*)(g_outA + (size_t)v * NH)     = m0;
    *(float4*)(g_outA + (size_t)v * NH + 4) = m1;
}

// ---------------- edge scatter, F=8 (2 lanes per edge, red.v4) --------------
template <bool COMPUTE_W>
__global__ void __launch_bounds__(512)
k_scatter8() {
    int stride = gridDim.x * blockDim.x;
    for (int gid = blockIdx.x * blockDim.x + threadIdx.x;
         gid < 2 * NEDGE; gid += stride) {
        int e = gid >> 1;
        int o = (gid & 1) * 4;
        int2 si = __ldg(&g_SI[e]);
        int s = si.x, i = si.y;
        float w;
        if (COMPUTE_W) {
            w = 0.125f * __ldg(g_dinv + s) * __ldg(g_dinv + i);
            if (o == 0) g_w[e] = w;
        } else {
            w = __ldg(g_w + e);
        }
        float4 mi = *(const float4*)(g_M + (size_t)i * 8 + o);
        float4 ms = *(const float4*)(g_M + (size_t)s * 8 + o);
        red_add4(g_outA + (size_t)s * 8 + o, w * mi.x, w * mi.y, w * mi.z, w * mi.w);
        red_add4(g_outA + (size_t)i * 8 + o, w * ms.x, w * ms.y, w * ms.z, w * ms.w);
    }
}

// ---------------- edge scatter, F=16 (4 lanes per edge, red.v4) -------------
__global__ void __launch_bounds__(512)
k_scatter16() {
    int stride = gridDim.x * blockDim.x;
    for (int gid = blockIdx.x * blockDim.x + threadIdx.x;
         gid < 4 * NEDGE; gid += stride) {
        int e = gid >> 2;
        int o = (gid & 3) * 4;
        int2 si = __ldg(&g_SI[e]);
        int s = si.x, i = si.y;
        float w = __ldg(g_w + e);
        float4 mi = *(const float4*)(g_M + (size_t)i * 16 + o);
        float4 ms = *(const float4*)(g_M + (size_t)s * 16 + o);
        red_add4(g_outB + (size_t)s * 16 + o, w * mi.x, w * mi.y, w * mi.z, w * mi.w);
        red_add4(g_outB + (size_t)i * 16 + o, w * ms.x, w * ms.y, w * ms.z, w * ms.w);
    }
}

// ---------------- dense layer: H = relu(outA + b_prev); M = H@W; out = d^2*M
// FIN fixed at 8 (outA stride 8). FOUT = 8 (write outA in-place) or 16 (outB).
template <int FOUT, bool TO_B>
__global__ void __launch_bounds__(256)
k_layer(const float* __restrict__ W, const float* __restrict__ b) {
    int v = blockIdx.x * blockDim.x + threadIdx.x;
    if (v >= NV) return;

    // hoist weights/bias into registers before the FMA loop
    float wreg[8 * FOUT];
#pragma unroll
    for (int t = 0; t < 8 * FOUT; t++) wreg[t] = __ldg(W + t);
    float breg[8];
#pragma unroll
    for (int k = 0; k < 8; k++) breg[k] = __ldg(b + k);

    float4 h0 = *(const float4*)(g_outA + (size_t)v * 8);
    float4 h1 = *(const float4*)(g_outA + (size_t)v * 8 + 4);
    float h[8] = {h0.x, h0.y, h0.z, h0.w, h1.x, h1.y, h1.z, h1.w};
#pragma unroll
    for (int k = 0; k < 8; k++) h[k] = fmaxf(h[k] + breg[k], 0.0f);

    float d  = g_dinv[v];
    float dd = d * d;
    float m[FOUT];
#pragma unroll
    for (int j = 0; j < FOUT; j++) m[j] = 0.0f;
#pragma unroll
    for (int k = 0; k < 8; k++) {
        float hk = h[k];
#pragma unroll
        for (int j = 0; j < FOUT; j++) m[j] += hk * wreg[k * FOUT + j];
    }
    float* Mrow = g_M + (size_t)v * FOUT;
    float* Orow = (TO_B ? g_outB : g_outA) + (size_t)v * FOUT;
#pragma unroll
    for (int j = 0; j < FOUT; j += 4) {
        *(float4*)(Mrow + j) = make_float4(m[j], m[j+1], m[j+2], m[j+3]);
        *(float4*)(Orow + j) = make_float4(dd*m[j], dd*m[j+1], dd*m[j+2], dd*m[j+3]);
    }
}

// ---------------- final: relu(outB + b3) @ fc_w + fc_b -> sigmoid -----------
__global__ void __launch_bounds__(256)
k_final(const float* __restrict__ b3,
        const float* __restrict__ fcw,
        const float* __restrict__ fcb,
        float* __restrict__ out) {
    int v = blockIdx.x * blockDim.x + threadIdx.x;
    if (v >= NV) return;
    float acc = __ldg(fcb);
#pragma unroll
    for (int j4 = 0; j4 < NC; j4 += 4) {
        float4 x = *(const float4*)(g_outB + (size_t)v * NC + j4);
        acc += fmaxf(x.x + __ldg(b3 + j4 + 0), 0.0f) * __ldg(fcw + j4 + 0);
        acc += fmaxf(x.y + __ldg(b3 + j4 + 1), 0.0f) * __ldg(fcw + j4 + 1);
        acc += fmaxf(x.z + __ldg(b3 + j4 + 2), 0.0f) * __ldg(fcw + j4 + 2);
        acc += fmaxf(x.w + __ldg(b3 + j4 + 3), 0.0f) * __ldg(fcw + j4 + 3);
    }
    out[v] = 1.0f / (1.0f + expf(-acc));
}

// ---------------- launch ----------------------------------------------------
extern "C" void kernel_launch(void* const* d_in, const int* in_sizes, int n_in,
                              void* d_out, int out_size) {
    const float* X   = (const float*)d_in[0];
    const void*  E   = d_in[1];
    const float* rv  = (const float*)d_in[2];
    const float* W1  = (const float*)d_in[3];
    const float* b1  = (const float*)d_in[4];
    const float* W2  = (const float*)d_in[5];
    const float* b2  = (const float*)d_in[6];
    const float* W3  = (const float*)d_in[7];
    const float* b3  = (const float*)d_in[8];
    const float* fcw = (const float*)d_in[9];
    const float* fcb = (const float*)d_in[10];
    float* out = (float*)d_out;

    const int B = 256;
    const int BS = 512;                       // scatter block size
    const int SCAT_BLOCKS = 148 * 16;         // grid-stride, ~1 wave of 512-thr CTAs

    k_detect<<<1, 256>>>((const int*)E);
    {
        long long threads = (long long)NV * 32;
        int blocks = (int)((threads + B - 1) / B);
        k_proj_xw1<<<blocks, B>>>(X, rv, W1);
    }
    k_edges<<<(NEDGE / 2 + B - 1) / B, B>>>(E);
    k_dinv_scale<<<(NV + B - 1) / B, B>>>();
    k_scatter8<true><<<SCAT_BLOCKS, BS>>>();
    k_layer<8, false><<<(NV + B - 1) / B, B>>>(W2, b1);
    k_scatter8<false><<<SCAT_BLOCKS, BS>>>();
    k_layer<16, true><<<(NV + B - 1) / B, B>>>(W3, b2);
    k_scatter16<<<SCAT_BLOCKS, BS>>>();
    k_final<<<(NV + B - 1) / B, B>>>(b3, fcw, fcb, out);
}